// round 7
// baseline (speedup 1.0000x reference)
#include <cuda_runtime.h>
#include <cuda_bf16.h>
#include <cstdint>

// CausalAttention B=8, S=2048, D=1024 fp32 via split-bf16 mma.sync (HMMA) GEMMs.
//   fp32 x = hi + lo (bf16);  A*B ~= Ahi*Bhi + Ahi*Blo + Alo*Bhi  (fp32 accum)
// R7: fused QKV projection (N=3072, epilogue dispatch), bf16 V transpose
//     (no fp32 roundtrip), causal-limited softmax. GEMM core = R6 fused 3-pass.

constexpr int B_ = 8;
constexpr int S_ = 2048;
constexpr int D_ = 1024;
constexpr int MTOT = B_ * S_;          // 16384

// ---------------- scratch (device globals; allocation-free) ----------------
__device__ __nv_bfloat16 g_xh[MTOT * D_], g_xl[MTOT * D_];
__device__ __nv_bfloat16 g_Wth[3][D_ * D_], g_Wtl[3][D_ * D_];   // concat [3*D, D]
__device__ __nv_bfloat16 g_QKVh[3][(size_t)MTOT * D_];           // Q,K,V hi [S,D]
__device__ __nv_bfloat16 g_QKVl[3][(size_t)MTOT * D_];           // Q,K,V lo
__device__ __nv_bfloat16 g_Vth[MTOT * D_], g_Vtl[MTOT * D_];     // [B][D][S]
__device__ float         g_Sc[(size_t)B_ * S_ * S_];
__device__ __nv_bfloat16 g_Ph[(size_t)B_ * S_ * S_], g_Pl[(size_t)B_ * S_ * S_];

// ---------------- helpers ----------------
__device__ __forceinline__ uint32_t smem_u32(const void* p) {
    uint32_t a;
    asm("{ .reg .u64 t; cvta.to.shared.u64 t, %1; cvt.u32.u64 %0, t; }"
        : "=r"(a) : "l"(p));
    return a;
}
__device__ __forceinline__ void cp_async16(uint32_t dst, const void* src) {
    asm volatile("cp.async.cg.shared.global [%0], [%1], 16;"
                 :: "r"(dst), "l"(__cvta_generic_to_global(src)) : "memory");
}
__device__ __forceinline__ void cp_commit() {
    asm volatile("cp.async.commit_group;" ::: "memory");
}
template <int N>
__device__ __forceinline__ void cp_wait() {
    asm volatile("cp.async.wait_group %0;" :: "n"(N) : "memory");
}
__device__ __forceinline__ void ldm_x4(uint32_t* r, uint32_t addr) {
    asm volatile("ldmatrix.sync.aligned.m8n8.x4.shared.b16 {%0,%1,%2,%3}, [%4];"
                 : "=r"(r[0]), "=r"(r[1]), "=r"(r[2]), "=r"(r[3]) : "r"(addr));
}
__device__ __forceinline__ void mma16816(float* c, const uint32_t* a,
                                         uint32_t b0, uint32_t b1) {
    asm volatile(
        "mma.sync.aligned.m16n8k16.row.col.f32.bf16.bf16.f32 "
        "{%0,%1,%2,%3}, {%4,%5,%6,%7}, {%8,%9}, {%0,%1,%2,%3};"
        : "+f"(c[0]), "+f"(c[1]), "+f"(c[2]), "+f"(c[3])
        : "r"(a[0]), "r"(a[1]), "r"(a[2]), "r"(a[3]), "r"(b0), "r"(b1));
}

// ---------------- split / transpose / softmax kernels ----------------
__global__ __launch_bounds__(256)
void split_f32(const float* __restrict__ in, __nv_bfloat16* __restrict__ h,
               __nv_bfloat16* __restrict__ l, int n4) {
    int i = blockIdx.x * 256 + threadIdx.x;
    if (i >= n4) return;
    float4 v = *reinterpret_cast<const float4*>(in + (size_t)i * 4);
    __nv_bfloat16 h0 = __float2bfloat16(v.x), h1 = __float2bfloat16(v.y);
    __nv_bfloat16 h2 = __float2bfloat16(v.z), h3 = __float2bfloat16(v.w);
    __nv_bfloat162 hp0{h0, h1}, hp1{h2, h3};
    __nv_bfloat162 lp0 = __floats2bfloat162_rn(v.x - __bfloat162float(h0),
                                               v.y - __bfloat162float(h1));
    __nv_bfloat162 lp1 = __floats2bfloat162_rn(v.z - __bfloat162float(h2),
                                               v.w - __bfloat162float(h3));
    uint2 hu, lu;
    hu.x = *reinterpret_cast<uint32_t*>(&hp0); hu.y = *reinterpret_cast<uint32_t*>(&hp1);
    lu.x = *reinterpret_cast<uint32_t*>(&lp0); lu.y = *reinterpret_cast<uint32_t*>(&lp1);
    *reinterpret_cast<uint2*>(h + (size_t)i * 4) = hu;
    *reinterpret_cast<uint2*>(l + (size_t)i * 4) = lu;
}

// fp32 in -> transposed split bf16 (weights)
__global__ __launch_bounds__(256)
void transpose_split(const float* __restrict__ in, __nv_bfloat16* __restrict__ oh,
                     __nv_bfloat16* __restrict__ ol, int R, int C) {
    __shared__ float t[32][33];
    int c0 = blockIdx.x * 32, r0 = blockIdx.y * 32;
    int tx = threadIdx.x;
#pragma unroll
    for (int j = 0; j < 4; j++) {
        int ty = threadIdx.y * 4 + j;
        t[ty][tx] = in[(size_t)(r0 + ty) * C + c0 + tx];
    }
    __syncthreads();
#pragma unroll
    for (int j = 0; j < 4; j++) {
        int ty = threadIdx.y * 4 + j;
        float v = t[tx][ty];
        __nv_bfloat16 hv = __float2bfloat16(v);
        size_t o = (size_t)(c0 + ty) * R + r0 + tx;
        oh[o] = hv;
        ol[o] = __float2bfloat16(v - __bfloat162float(hv));
    }
}

// bf16 pair transpose: per batch [S,D] -> [D,S]
__global__ __launch_bounds__(256)
void transpose_bf2(const __nv_bfloat16* __restrict__ ih,
                   const __nv_bfloat16* __restrict__ il,
                   __nv_bfloat16* __restrict__ oh, __nv_bfloat16* __restrict__ ol) {
    __shared__ __nv_bfloat16 th[32][34], tl[32][34];
    int z = blockIdx.z;
    ih += (size_t)z * S_ * D_; il += (size_t)z * S_ * D_;
    oh += (size_t)z * D_ * S_; ol += (size_t)z * D_ * S_;
    int c0 = blockIdx.x * 32, r0 = blockIdx.y * 32;
    int tx = threadIdx.x;
#pragma unroll
    for (int j = 0; j < 4; j++) {
        int ty = threadIdx.y * 4 + j;
        size_t o = (size_t)(r0 + ty) * D_ + c0 + tx;
        th[ty][tx] = ih[o];
        tl[ty][tx] = il[o];
    }
    __syncthreads();
#pragma unroll
    for (int j = 0; j < 4; j++) {
        int ty = threadIdx.y * 4 + j;
        size_t o = (size_t)(c0 + ty) * S_ + r0 + tx;
        oh[o] = th[tx][ty];
        ol[o] = tl[tx][ty];
    }
}

// row-wise causal softmax of Sc/32 -> split bf16 P.
// Reads only j<n; writes zeros only up to next 128 boundary (PV's K extent).
__global__ __launch_bounds__(256)
void softmax_split(const float* __restrict__ Sc, __nv_bfloat16* __restrict__ Ph,
                   __nv_bfloat16* __restrict__ Pl) {
    const int r = blockIdx.x, i = r % S_;
    const size_t off = (size_t)r * S_;
    const float* row = Sc + off;
    const int n = i + 1;
    const int nIt = (n + 255) >> 8;
    const int kLim = (n + 127) & ~127;           // write extent (zeros beyond n)
    const float scale = 0.03125f;                // 1/sqrt(1024)
    const int tid = threadIdx.x;

    float vals[8];
    float m = -INFINITY;
    for (int it = 0; it < nIt; it++) {
        int j = it * 256 + tid;
        float v = (j < n) ? row[j] * scale : -INFINITY;
        vals[it] = v; m = fmaxf(m, v);
    }
    __shared__ float red[8];
#pragma unroll
    for (int o = 16; o > 0; o >>= 1) m = fmaxf(m, __shfl_xor_sync(~0u, m, o));
    if ((tid & 31) == 0) red[tid >> 5] = m;
    __syncthreads();
    float M = red[0];
#pragma unroll
    for (int w = 1; w < 8; w++) M = fmaxf(M, red[w]);
    __syncthreads();
    float ssum = 0.f;
    for (int it = 0; it < nIt; it++) {
        int j = it * 256 + tid;
        float e = (j < n) ? __expf(vals[it] - M) : 0.f;
        vals[it] = e; ssum += e;
    }
#pragma unroll
    for (int o = 16; o > 0; o >>= 1) ssum += __shfl_xor_sync(~0u, ssum, o);
    if ((tid & 31) == 0) red[tid >> 5] = ssum;
    __syncthreads();
    float T = 0.f;
#pragma unroll
    for (int w = 0; w < 8; w++) T += red[w];
    const float inv = 1.f / T;
    for (int it = 0; it < nIt; it++) {
        int j = it * 256 + tid;
        if (j < kLim) {
            float v = (j < n) ? vals[it] * inv : 0.f;
            __nv_bfloat16 hv = __float2bfloat16(v);
            Ph[off + j] = hv;
            Pl[off + j] = __float2bfloat16(v - __bfloat162float(hv));
        }
    }
}

// ---------------- fused HMMA split-bf16 GEMM ----------------
// C[M,N] = (Ah+Al)[M,K] * (Bh+Bl)[N,K]^T, tile 128x128, BK=64, 8 warps (32x64).
// Per chunk: load Ah/Al/Bh/Bl tiles (64 KB), issue Ah*Bh + Ah*Bl + Al*Bh.
// EP: 0 -> fp32 to Cf;  1 -> split bf16 to Ch/Cl.
// QKV: epilogue routes 128-col tile to buffer colBase>>10 (Ch/Cl = [3][MTOT*D]).
constexpr int TILE_B = 16384;                    // one 128x64 bf16 tile
constexpr int STG_BYTES = 4 * TILE_B;            // Ah,Al,Bh,Bl = 64 KB
constexpr int SMEM_BYTES = 2 * STG_BYTES;        // 128 KB

template <int EP, bool CSKIP, bool CLIMK, bool QKV>
__global__ __launch_bounds__(256, 1)
void hmma_gemm(const __nv_bfloat16* __restrict__ Ah, const __nv_bfloat16* __restrict__ Al,
               const __nv_bfloat16* __restrict__ Bh, const __nv_bfloat16* __restrict__ Bl,
               float* __restrict__ Cf, __nv_bfloat16* __restrict__ Ch,
               __nv_bfloat16* __restrict__ Cl,
               int N, int K, size_t sA, size_t sB, size_t sC)
{
    const int rowBase = blockIdx.y * 128, colBase = blockIdx.x * 128;
    if (CSKIP && colBase > rowBase) return;
    const int kEnd = CLIMK ? (rowBase + 128) : K;
    const int NC = kEnd >> 6;                     // chunks of 64 K

    extern __shared__ char smem[];
    const uint32_t sbase = smem_u32(smem);

    const size_t zA = (size_t)blockIdx.z * sA, zB = (size_t)blockIdx.z * sB;
    Ah += zA; Al += zA; Bh += zB; Bl += zB;

    const int tid = threadIdx.x, wid = tid >> 5, lid = tid & 31;
    const int wr = wid & 3, wc = wid >> 2;         // warp grid 4(m) x 2(n)

    uint32_t aRel[2], aXor[2];
#pragma unroll
    for (int mt = 0; mt < 2; mt++) {
        int r = wr * 32 + mt * 16 + (lid & 15);
        aRel[mt] = r * 128;
        aXor[mt] = (r & 7) << 4;
    }
    const uint32_t aHalf = (lid >> 4) * 16;
    const int g = lid >> 3;
    uint32_t bRel[4], bXor[4];
#pragma unroll
    for (int nt = 0; nt < 4; nt++) {
        int r = wc * 64 + nt * 16 + ((g & 1) << 3) + (lid & 7);
        bRel[nt] = r * 128;
        bXor[nt] = (r & 7) << 4;
    }
    const uint32_t bHalf = (g >> 1) * 16;

    float acc[2][8][4];
#pragma unroll
    for (int i = 0; i < 2; i++)
#pragma unroll
        for (int j = 0; j < 8; j++)
#pragma unroll
            for (int k = 0; k < 4; k++) acc[i][j][k] = 0.f;

    auto loadChunk = [&](int c, int buf) {
        const int k0 = c << 6;
        const uint32_t st = sbase + buf * STG_BYTES;
#pragma unroll
        for (int j = 0; j < 4; j++) {
            int idx = j * 256 + tid;                   // 0..1023
            int row = idx >> 3, col = idx & 7;         // 128 rows x 8 cols of 16B
            uint32_t off = row * 128 + ((col * 16) ^ ((row & 7) << 4));
            size_t ga = (size_t)(rowBase + row) * K + k0 + col * 8;
            size_t gb = (size_t)(colBase + row) * K + k0 + col * 8;
            cp_async16(st + off,              Ah + ga);
            cp_async16(st + TILE_B + off,     Al + ga);
            cp_async16(st + 2 * TILE_B + off, Bh + gb);
            cp_async16(st + 3 * TILE_B + off, Bl + gb);
        }
        cp_commit();
    };

    loadChunk(0, 0);

    for (int c = 0; c < NC; c++) {
        const int buf = c & 1;
        cp_wait<0>();
        __syncthreads();
        if (c + 1 < NC) loadChunk(c + 1, buf ^ 1);

        const uint32_t sAh = sbase + buf * STG_BYTES;
        const uint32_t sAl = sAh + TILE_B;
        const uint32_t sBh = sAh + 2 * TILE_B;
        const uint32_t sBl = sAh + 3 * TILE_B;
#pragma unroll
        for (int ks = 0; ks < 4; ks++) {
            const uint32_t kb = ks * 32;
            uint32_t ah[2][4], al[2][4], bh[4][4], bl[4][4];
#pragma unroll
            for (int nt = 0; nt < 4; nt++) {
                uint32_t o = bRel[nt] + ((kb + bHalf) ^ bXor[nt]);
                ldm_x4(bh[nt], sBh + o);
                ldm_x4(bl[nt], sBl + o);
            }
#pragma unroll
            for (int mt = 0; mt < 2; mt++) {
                uint32_t o = aRel[mt] + ((kb + aHalf) ^ aXor[mt]);
                ldm_x4(ah[mt], sAh + o);
                ldm_x4(al[mt], sAl + o);
            }
#pragma unroll
            for (int mt = 0; mt < 2; mt++)
#pragma unroll
                for (int nt = 0; nt < 4; nt++) {
                    float* c0 = acc[mt][2 * nt];
                    float* c1 = acc[mt][2 * nt + 1];
                    mma16816(c0, ah[mt], bh[nt][0], bh[nt][2]);
                    mma16816(c1, ah[mt], bh[nt][1], bh[nt][3]);
                    mma16816(c0, ah[mt], bl[nt][0], bl[nt][2]);
                    mma16816(c1, ah[mt], bl[nt][1], bl[nt][3]);
                    mma16816(c0, al[mt], bh[nt][0], bh[nt][2]);
                    mma16816(c1, al[mt], bh[nt][1], bh[nt][3]);
                }
        }
        __syncthreads();
    }

    // ---- epilogue ----
    int cb2 = colBase;
    if (QKV) {
        int sel = colBase >> 10;                  // 0=Q, 1=K, 2=V
        Ch += (size_t)sel * MTOT * D_;
        Cl += (size_t)sel * MTOT * D_;
        cb2 = colBase & 1023;
    }
    const int colW = cb2 + wc * 64 + (lid & 3) * 2;
#pragma unroll
    for (int mt = 0; mt < 2; mt++) {
        const int row0 = rowBase + wr * 32 + mt * 16 + (lid >> 2);
#pragma unroll
        for (int nt = 0; nt < 8; nt++) {
            const int col = colW + nt * 8;
            const float* cc = acc[mt][nt];
            if (EP == 0) {
                float* base = Cf + (size_t)blockIdx.z * sC;
                *reinterpret_cast<float2*>(base + (size_t)row0 * N + col) =
                    make_float2(cc[0], cc[1]);
                *reinterpret_cast<float2*>(base + (size_t)(row0 + 8) * N + col) =
                    make_float2(cc[2], cc[3]);
            } else {
#pragma unroll
                for (int h = 0; h < 2; h++) {
                    float f0 = cc[2 * h], f1 = cc[2 * h + 1];
                    __nv_bfloat16 h0 = __float2bfloat16(f0), h1 = __float2bfloat16(f1);
                    __nv_bfloat162 hp{h0, h1};
                    __nv_bfloat162 lp = __floats2bfloat162_rn(
                        f0 - __bfloat162float(h0), f1 - __bfloat162float(h1));
                    size_t o = (size_t)(row0 + h * 8) * N + col;
                    *reinterpret_cast<uint32_t*>(Ch + o) =
                        *reinterpret_cast<uint32_t*>(&hp);
                    *reinterpret_cast<uint32_t*>(Cl + o) =
                        *reinterpret_cast<uint32_t*>(&lp);
                }
            }
        }
    }
}

// ---------------- launch ----------------
extern "C" void kernel_launch(void* const* d_in, const int* in_sizes, int n_in,
                              void* d_out, int out_size)
{
    const float* x  = (const float*)d_in[0];
    const float* Wq = (const float*)d_in[1];
    const float* Wk = (const float*)d_in[2];
    const float* Wv = (const float*)d_in[3];
    float* out = (float*)d_out;

    __nv_bfloat16 *xh, *xl, *Wth, *Wtl, *QKVh, *QKVl, *Vth, *Vtl, *Ph, *Pl;
    float *Sc;
    cudaGetSymbolAddress((void**)&xh, g_xh);     cudaGetSymbolAddress((void**)&xl, g_xl);
    cudaGetSymbolAddress((void**)&Wth, g_Wth);   cudaGetSymbolAddress((void**)&Wtl, g_Wtl);
    cudaGetSymbolAddress((void**)&QKVh, g_QKVh); cudaGetSymbolAddress((void**)&QKVl, g_QKVl);
    cudaGetSymbolAddress((void**)&Vth, g_Vth);   cudaGetSymbolAddress((void**)&Vtl, g_Vtl);
    cudaGetSymbolAddress((void**)&Sc, g_Sc);
    cudaGetSymbolAddress((void**)&Ph, g_Ph);     cudaGetSymbolAddress((void**)&Pl, g_Pl);

    const size_t QD = (size_t)MTOT * D_;
    __nv_bfloat16 *Qh = QKVh,          *Ql = QKVl;
    __nv_bfloat16 *Kh = QKVh + QD,     *Kl = QKVl + QD;
    __nv_bfloat16 *Vh = QKVh + 2 * QD, *Vl = QKVl + 2 * QD;

    cudaFuncSetAttribute(hmma_gemm<1, false, false, true>,
                         cudaFuncAttributeMaxDynamicSharedMemorySize, SMEM_BYTES);
    cudaFuncSetAttribute(hmma_gemm<0, true, false, false>,
                         cudaFuncAttributeMaxDynamicSharedMemorySize, SMEM_BYTES);
    cudaFuncSetAttribute(hmma_gemm<0, false, true, false>,
                         cudaFuncAttributeMaxDynamicSharedMemorySize, SMEM_BYTES);

    // 1. split x
    split_f32<<<(MTOT * D_ / 4 + 255) / 256, 256>>>(x, xh, xl, MTOT * D_ / 4);
    // 2. transpose + split weights into concatenated Wt [3*D, D]
    dim3 tb(32, 8);
    transpose_split<<<dim3(32, 32, 1), tb>>>(Wq, Wth, Wtl, D_, D_);
    transpose_split<<<dim3(32, 32, 1), tb>>>(Wk, Wth + (size_t)D_ * D_,
                                             Wtl + (size_t)D_ * D_, D_, D_);
    transpose_split<<<dim3(32, 32, 1), tb>>>(Wv, Wth + 2 * (size_t)D_ * D_,
                                             Wtl + 2 * (size_t)D_ * D_, D_, D_);

    // 3. fused QKV projection: (16384 x 1024) @ (1024 x 3072)
    hmma_gemm<1, false, false, true><<<dim3(3 * D_ / 128, MTOT / 128, 1), 256, SMEM_BYTES>>>(
        xh, xl, Wth, Wtl, nullptr, QKVh, QKVl, D_, D_, 0, 0, 0);

    // 4. V -> Vt (bf16 pair transpose, per batch [S,D] -> [D,S])
    transpose_bf2<<<dim3(D_ / 32, S_ / 32, B_), tb>>>(Vh, Vl, Vth, Vtl);

    // 5. scores = Q K^T (lower-triangular blocks), fp32
    hmma_gemm<0, true, false, false><<<dim3(S_ / 128, S_ / 128, B_), 256, SMEM_BYTES>>>(
        Qh, Ql, Kh, Kl, Sc, nullptr, nullptr, S_, D_,
        (size_t)S_ * D_, (size_t)S_ * D_, (size_t)S_ * S_);

    // 6. causal-limited softmax -> split P
    softmax_split<<<B_ * S_, 256>>>(Sc, Ph, Pl);

    // 7. out = P V  (K limited to rowBase+128)
    hmma_gemm<0, false, true, false><<<dim3(D_ / 128, S_ / 128, B_), 256, SMEM_BYTES>>>(
        Ph, Pl, Vth, Vtl, out, nullptr, nullptr, D_, S_,
        (size_t)S_ * S_, (size_t)D_ * S_, (size_t)S_ * D_);
}

// round 8
// speedup vs baseline: 1.5128x; 1.5128x over previous
#include <cuda_runtime.h>
#include <cuda_fp16.h>
#include <cstdint>

// CausalAttention B=8, S=2048, D=1024 fp32 via fp16 2-term mma.sync GEMMs.
//   A = Ah + Al (two fp16, exact to 22 bits), B ~= Bh (one fp16).
//   C = Ah*Bh + Al*Bh = A*Bh in fp32 accum — error is only B's fp16 rounding.
// R8: 2 MMAs per 16-K (was 3), B-side lo eliminated, 96KB smem -> 2 CTA/SM.

constexpr int B_ = 8;
constexpr int S_ = 2048;
constexpr int D_ = 1024;
constexpr int MTOT = B_ * S_;          // 16384

// ---------------- scratch (device globals; allocation-free) ----------------
__device__ __half g_xh[MTOT * D_], g_xl[MTOT * D_];
__device__ __half g_Wth[3][D_ * D_];                     // W^T hi only [3][D,D]
__device__ __half g_Qh[MTOT * D_], g_Ql[MTOT * D_];      // Q 2-term (A side)
__device__ __half g_Kh[MTOT * D_];                       // K hi only (B side)
__device__ __half g_Vh[MTOT * D_];                       // V hi only
__device__ __half g_Vth[MTOT * D_];                      // V^T hi [B][D][S]
__device__ float  g_Sc[(size_t)B_ * S_ * S_];
__device__ __half g_Ph[(size_t)B_ * S_ * S_], g_Pl[(size_t)B_ * S_ * S_];

// ---------------- helpers ----------------
__device__ __forceinline__ uint32_t smem_u32(const void* p) {
    uint32_t a;
    asm("{ .reg .u64 t; cvta.to.shared.u64 t, %1; cvt.u32.u64 %0, t; }"
        : "=r"(a) : "l"(p));
    return a;
}
__device__ __forceinline__ void cp_async16(uint32_t dst, const void* src) {
    asm volatile("cp.async.cg.shared.global [%0], [%1], 16;"
                 :: "r"(dst), "l"(__cvta_generic_to_global(src)) : "memory");
}
__device__ __forceinline__ void cp_commit() {
    asm volatile("cp.async.commit_group;" ::: "memory");
}
template <int N>
__device__ __forceinline__ void cp_wait() {
    asm volatile("cp.async.wait_group %0;" :: "n"(N) : "memory");
}
__device__ __forceinline__ void ldm_x4(uint32_t* r, uint32_t addr) {
    asm volatile("ldmatrix.sync.aligned.m8n8.x4.shared.b16 {%0,%1,%2,%3}, [%4];"
                 : "=r"(r[0]), "=r"(r[1]), "=r"(r[2]), "=r"(r[3]) : "r"(addr));
}
__device__ __forceinline__ void mma16816(float* c, const uint32_t* a,
                                         uint32_t b0, uint32_t b1) {
    asm volatile(
        "mma.sync.aligned.m16n8k16.row.col.f32.f16.f16.f32 "
        "{%0,%1,%2,%3}, {%4,%5,%6,%7}, {%8,%9}, {%0,%1,%2,%3};"
        : "+f"(c[0]), "+f"(c[1]), "+f"(c[2]), "+f"(c[3])
        : "r"(a[0]), "r"(a[1]), "r"(a[2]), "r"(a[3]), "r"(b0), "r"(b1));
}

// ---------------- split / transpose / softmax kernels ----------------
// fp32 -> fp16 hi + lo (A-side operands)
__global__ __launch_bounds__(256)
void split_f32h(const float* __restrict__ in, __half* __restrict__ h,
                __half* __restrict__ l, int n4) {
    int i = blockIdx.x * 256 + threadIdx.x;
    if (i >= n4) return;
    float4 v = *reinterpret_cast<const float4*>(in + (size_t)i * 4);
    __half h0 = __float2half_rn(v.x), h1 = __float2half_rn(v.y);
    __half h2 = __float2half_rn(v.z), h3 = __float2half_rn(v.w);
    __half2 hp0{h0, h1}, hp1{h2, h3};
    __half2 lp0 = __floats2half2_rn(v.x - __half2float(h0), v.y - __half2float(h1));
    __half2 lp1 = __floats2half2_rn(v.z - __half2float(h2), v.w - __half2float(h3));
    uint2 hu, lu;
    hu.x = *reinterpret_cast<uint32_t*>(&hp0); hu.y = *reinterpret_cast<uint32_t*>(&hp1);
    lu.x = *reinterpret_cast<uint32_t*>(&lp0); lu.y = *reinterpret_cast<uint32_t*>(&lp1);
    *reinterpret_cast<uint2*>(h + (size_t)i * 4) = hu;
    *reinterpret_cast<uint2*>(l + (size_t)i * 4) = lu;
}

// fp32 W [R,C] -> transposed fp16 hi only [C,R]
__global__ __launch_bounds__(256)
void transpose_h(const float* __restrict__ in, __half* __restrict__ oh, int R, int C) {
    __shared__ float t[32][33];
    int c0 = blockIdx.x * 32, r0 = blockIdx.y * 32;
    int tx = threadIdx.x;
#pragma unroll
    for (int j = 0; j < 4; j++) {
        int ty = threadIdx.y * 4 + j;
        t[ty][tx] = in[(size_t)(r0 + ty) * C + c0 + tx];
    }
    __syncthreads();
#pragma unroll
    for (int j = 0; j < 4; j++) {
        int ty = threadIdx.y * 4 + j;
        oh[(size_t)(c0 + ty) * R + r0 + tx] = __float2half_rn(t[tx][ty]);
    }
}

// fp16 V [S,D] -> [D,S] per batch
__global__ __launch_bounds__(256)
void transpose_half(const __half* __restrict__ ih, __half* __restrict__ oh) {
    __shared__ __half th[32][34];
    int z = blockIdx.z;
    ih += (size_t)z * S_ * D_;
    oh += (size_t)z * D_ * S_;
    int c0 = blockIdx.x * 32, r0 = blockIdx.y * 32;
    int tx = threadIdx.x;
#pragma unroll
    for (int j = 0; j < 4; j++) {
        int ty = threadIdx.y * 4 + j;
        th[ty][tx] = ih[(size_t)(r0 + ty) * D_ + c0 + tx];
    }
    __syncthreads();
#pragma unroll
    for (int j = 0; j < 4; j++) {
        int ty = threadIdx.y * 4 + j;
        oh[(size_t)(c0 + ty) * S_ + r0 + tx] = th[tx][ty];
    }
}

// row-wise causal softmax of Sc/32 -> split fp16 P (2-term A-side).
// Reads only j<n; writes up to the row block's 128 boundary.
__global__ __launch_bounds__(256)
void softmax_split(const float* __restrict__ Sc, __half* __restrict__ Ph,
                   __half* __restrict__ Pl) {
    const int r = blockIdx.x, i = r % S_;
    const size_t off = (size_t)r * S_;
    const float* row = Sc + off;
    const int n = i + 1;
    const int nIt = (n + 255) >> 8;
    const int kLim = (n + 127) & ~127;
    const float scale = 0.03125f;                // 1/sqrt(1024)
    const int tid = threadIdx.x;

    float vals[8];
    float m = -INFINITY;
    for (int it = 0; it < nIt; it++) {
        int j = it * 256 + tid;
        float v = (j < n) ? row[j] * scale : -INFINITY;
        vals[it] = v; m = fmaxf(m, v);
    }
    __shared__ float red[8];
#pragma unroll
    for (int o = 16; o > 0; o >>= 1) m = fmaxf(m, __shfl_xor_sync(~0u, m, o));
    if ((tid & 31) == 0) red[tid >> 5] = m;
    __syncthreads();
    float M = red[0];
#pragma unroll
    for (int w = 1; w < 8; w++) M = fmaxf(M, red[w]);
    __syncthreads();
    float ssum = 0.f;
    for (int it = 0; it < nIt; it++) {
        int j = it * 256 + tid;
        float e = (j < n) ? __expf(vals[it] - M) : 0.f;
        vals[it] = e; ssum += e;
    }
#pragma unroll
    for (int o = 16; o > 0; o >>= 1) ssum += __shfl_xor_sync(~0u, ssum, o);
    if ((tid & 31) == 0) red[tid >> 5] = ssum;
    __syncthreads();
    float T = 0.f;
#pragma unroll
    for (int w = 0; w < 8; w++) T += red[w];
    const float inv = 1.f / T;
    for (int it = 0; it < nIt; it++) {
        int j = it * 256 + tid;
        if (j < kLim) {
            float v = (j < n) ? vals[it] * inv : 0.f;
            __half hv = __float2half_rn(v);
            Ph[off + j] = hv;
            Pl[off + j] = __float2half_rn(v - __half2float(hv));
        }
    }
}

// ---------------- fp16 2-term HMMA GEMM ----------------
// C[M,N] = (Ah+Al)[M,K] * Bh[N,K]^T, tile 128x128, BK=64, 8 warps (32x64).
// Per chunk: load Ah/Al/Bh tiles (48 KB). 2 MMAs per (mt,nt,ks).
// EP: 0 -> fp32 to Cf;  1 -> fp16 hi+lo (Ch,Cl);  2 -> fp16 hi only (Ch).
// CSKIP: skip blocks above causal diagonal.  CLIMK: kEnd = rowBase+128.
constexpr int TILE_B = 16384;                    // one 128x64 fp16 tile
constexpr int STG_BYTES = 3 * TILE_B;            // Ah,Al,Bh = 48 KB
constexpr int SMEM_BYTES = 2 * STG_BYTES;        // 96 KB

template <int EP, bool CSKIP, bool CLIMK>
__global__ __launch_bounds__(256, 2)
void hmma_gemm(const __half* __restrict__ Ah, const __half* __restrict__ Al,
               const __half* __restrict__ Bh,
               float* __restrict__ Cf, __half* __restrict__ Ch,
               __half* __restrict__ Cl,
               int N, int K, size_t sA, size_t sB, size_t sC)
{
    const int rowBase = blockIdx.y * 128, colBase = blockIdx.x * 128;
    if (CSKIP && colBase > rowBase) return;
    const int kEnd = CLIMK ? (rowBase + 128) : K;
    const int NC = kEnd >> 6;                     // chunks of 64 K

    extern __shared__ char smem[];
    const uint32_t sbase = smem_u32(smem);

    const size_t zA = (size_t)blockIdx.z * sA, zB = (size_t)blockIdx.z * sB;
    Ah += zA; Al += zA; Bh += zB;

    const int tid = threadIdx.x, wid = tid >> 5, lid = tid & 31;
    const int wr = wid & 3, wc = wid >> 2;         // warp grid 4(m) x 2(n)

    uint32_t aRel[2], aXor[2];
#pragma unroll
    for (int mt = 0; mt < 2; mt++) {
        int r = wr * 32 + mt * 16 + (lid & 15);
        aRel[mt] = r * 128;
        aXor[mt] = (r & 7) << 4;
    }
    const uint32_t aHalf = (lid >> 4) * 16;
    const int g = lid >> 3;
    uint32_t bRel[4], bXor[4];
#pragma unroll
    for (int nt = 0; nt < 4; nt++) {
        int r = wc * 64 + nt * 16 + ((g & 1) << 3) + (lid & 7);
        bRel[nt] = r * 128;
        bXor[nt] = (r & 7) << 4;
    }
    const uint32_t bHalf = (g >> 1) * 16;

    float acc[2][8][4];
#pragma unroll
    for (int i = 0; i < 2; i++)
#pragma unroll
        for (int j = 0; j < 8; j++)
#pragma unroll
            for (int k = 0; k < 4; k++) acc[i][j][k] = 0.f;

    auto loadChunk = [&](int c, int buf) {
        const int k0 = c << 6;
        const uint32_t st = sbase + buf * STG_BYTES;
#pragma unroll
        for (int j = 0; j < 4; j++) {
            int idx = j * 256 + tid;                   // 0..1023
            int row = idx >> 3, col = idx & 7;         // 128 rows x 8 cols of 16B
            uint32_t off = row * 128 + ((col * 16) ^ ((row & 7) << 4));
            size_t ga = (size_t)(rowBase + row) * K + k0 + col * 8;
            size_t gb = (size_t)(colBase + row) * K + k0 + col * 8;
            cp_async16(st + off,              Ah + ga);
            cp_async16(st + TILE_B + off,     Al + ga);
            cp_async16(st + 2 * TILE_B + off, Bh + gb);
        }
        cp_commit();
    };

    loadChunk(0, 0);

    for (int c = 0; c < NC; c++) {
        const int buf = c & 1;
        cp_wait<0>();
        __syncthreads();
        if (c + 1 < NC) loadChunk(c + 1, buf ^ 1);

        const uint32_t sAh = sbase + buf * STG_BYTES;
        const uint32_t sAl = sAh + TILE_B;
        const uint32_t sBh = sAh + 2 * TILE_B;
#pragma unroll
        for (int ks = 0; ks < 4; ks++) {
            const uint32_t kb = ks * 32;
            uint32_t ah[2][4], al[2][4], bh[4][4];
#pragma unroll
            for (int nt = 0; nt < 4; nt++)
                ldm_x4(bh[nt], sBh + bRel[nt] + ((kb + bHalf) ^ bXor[nt]));
#pragma unroll
            for (int mt = 0; mt < 2; mt++) {
                uint32_t o = aRel[mt] + ((kb + aHalf) ^ aXor[mt]);
                ldm_x4(ah[mt], sAh + o);
                ldm_x4(al[mt], sAl + o);
            }
#pragma unroll
            for (int mt = 0; mt < 2; mt++)
#pragma unroll
                for (int nt = 0; nt < 4; nt++) {
                    float* c0 = acc[mt][2 * nt];
                    float* c1 = acc[mt][2 * nt + 1];
                    mma16816(c0, ah[mt], bh[nt][0], bh[nt][2]);
                    mma16816(c1, ah[mt], bh[nt][1], bh[nt][3]);
                    mma16816(c0, al[mt], bh[nt][0], bh[nt][2]);
                    mma16816(c1, al[mt], bh[nt][1], bh[nt][3]);
                }
        }
        __syncthreads();
    }

    // ---- epilogue ----
    const int colW = colBase + wc * 64 + (lid & 3) * 2;
#pragma unroll
    for (int mt = 0; mt < 2; mt++) {
        const int row0 = rowBase + wr * 32 + mt * 16 + (lid >> 2);
#pragma unroll
        for (int nt = 0; nt < 8; nt++) {
            const int col = colW + nt * 8;
            const float* cc = acc[mt][nt];
            if (EP == 0) {
                float* base = Cf + (size_t)blockIdx.z * sC;
                *reinterpret_cast<float2*>(base + (size_t)row0 * N + col) =
                    make_float2(cc[0], cc[1]);
                *reinterpret_cast<float2*>(base + (size_t)(row0 + 8) * N + col) =
                    make_float2(cc[2], cc[3]);
            } else {
#pragma unroll
                for (int h = 0; h < 2; h++) {
                    float f0 = cc[2 * h], f1 = cc[2 * h + 1];
                    __half h0 = __float2half_rn(f0), h1 = __float2half_rn(f1);
                    __half2 hp{h0, h1};
                    size_t o = (size_t)(row0 + h * 8) * N + col;
                    *reinterpret_cast<uint32_t*>(Ch + o) =
                        *reinterpret_cast<uint32_t*>(&hp);
                    if (EP == 1) {
                        __half2 lp = __floats2half2_rn(f0 - __half2float(h0),
                                                       f1 - __half2float(h1));
                        *reinterpret_cast<uint32_t*>(Cl + o) =
                            *reinterpret_cast<uint32_t*>(&lp);
                    }
                }
            }
        }
    }
}

// ---------------- launch ----------------
extern "C" void kernel_launch(void* const* d_in, const int* in_sizes, int n_in,
                              void* d_out, int out_size)
{
    const float* x  = (const float*)d_in[0];
    const float* Wq = (const float*)d_in[1];
    const float* Wk = (const float*)d_in[2];
    const float* Wv = (const float*)d_in[3];
    float* out = (float*)d_out;

    __half *xh, *xl, *Wth, *Qh, *Ql, *Kh, *Vh, *Vth, *Ph, *Pl;
    float *Sc;
    cudaGetSymbolAddress((void**)&xh, g_xh);   cudaGetSymbolAddress((void**)&xl, g_xl);
    cudaGetSymbolAddress((void**)&Wth, g_Wth);
    cudaGetSymbolAddress((void**)&Qh, g_Qh);   cudaGetSymbolAddress((void**)&Ql, g_Ql);
    cudaGetSymbolAddress((void**)&Kh, g_Kh);   cudaGetSymbolAddress((void**)&Vh, g_Vh);
    cudaGetSymbolAddress((void**)&Vth, g_Vth);
    cudaGetSymbolAddress((void**)&Sc, g_Sc);
    cudaGetSymbolAddress((void**)&Ph, g_Ph);   cudaGetSymbolAddress((void**)&Pl, g_Pl);

    cudaFuncSetAttribute(hmma_gemm<1, false, false>,
                         cudaFuncAttributeMaxDynamicSharedMemorySize, SMEM_BYTES);
    cudaFuncSetAttribute(hmma_gemm<2, false, false>,
                         cudaFuncAttributeMaxDynamicSharedMemorySize, SMEM_BYTES);
    cudaFuncSetAttribute(hmma_gemm<0, true, false>,
                         cudaFuncAttributeMaxDynamicSharedMemorySize, SMEM_BYTES);
    cudaFuncSetAttribute(hmma_gemm<0, false, true>,
                         cudaFuncAttributeMaxDynamicSharedMemorySize, SMEM_BYTES);

    // 1. split x into fp16 hi/lo
    split_f32h<<<(MTOT * D_ / 4 + 255) / 256, 256>>>(x, xh, xl, MTOT * D_ / 4);
    // 2. transpose weights -> fp16 hi only [dout, din]
    dim3 tb(32, 8);
    transpose_h<<<dim3(32, 32, 1), tb>>>(Wq, Wth, D_, D_);
    transpose_h<<<dim3(32, 32, 1), tb>>>(Wk, Wth + (size_t)D_ * D_, D_, D_);
    transpose_h<<<dim3(32, 32, 1), tb>>>(Wv, Wth + 2 * (size_t)D_ * D_, D_, D_);

    // 3. projections: Q needs hi+lo (A side of QK); K,V need hi only (B sides)
    dim3 gp(D_ / 128, MTOT / 128, 1);
    hmma_gemm<1, false, false><<<gp, 256, SMEM_BYTES>>>(
        xh, xl, Wth, nullptr, Qh, Ql, D_, D_, 0, 0, 0);
    hmma_gemm<2, false, false><<<gp, 256, SMEM_BYTES>>>(
        xh, xl, Wth + (size_t)D_ * D_, nullptr, Kh, nullptr, D_, D_, 0, 0, 0);
    hmma_gemm<2, false, false><<<gp, 256, SMEM_BYTES>>>(
        xh, xl, Wth + 2 * (size_t)D_ * D_, nullptr, Vh, nullptr, D_, D_, 0, 0, 0);

    // 4. V -> Vt (fp16, per batch [S,D] -> [D,S])
    transpose_half<<<dim3(D_ / 32, S_ / 32, B_), tb>>>(Vh, Vth);

    // 5. scores = Q K^T (lower-triangular blocks), fp32
    hmma_gemm<0, true, false><<<dim3(S_ / 128, S_ / 128, B_), 256, SMEM_BYTES>>>(
        Qh, Ql, Kh, Sc, nullptr, nullptr, S_, D_,
        (size_t)S_ * D_, (size_t)S_ * D_, (size_t)S_ * S_);

    // 6. causal-limited softmax -> split fp16 P
    softmax_split<<<B_ * S_, 256>>>(Sc, Ph, Pl);

    // 7. out = P V  (K limited to rowBase+128)
    hmma_gemm<0, false, true><<<dim3(D_ / 128, S_ / 128, B_), 256, SMEM_BYTES>>>(
        Ph, Pl, Vth, out, nullptr, nullptr, D_, S_,
        (size_t)S_ * S_, (size_t)D_ * S_, (size_t)S_ * D_);
}